// round 12
// baseline (speedup 1.0000x reference)
#include <cuda_runtime.h>
#include <cuda_bf16.h>

#define BATCH   16384
#define EMBED   64
#define N_EDGES 524288
#define FULL    0xffffffffu
#define MLPGRID 592

// Fused scratch: [acc 4MB | cnt 64KB] zeroed by one graph memset node.
__device__ float g_scratch[BATCH * EMBED + BATCH];
#define G_ACC g_scratch
#define G_CNT (g_scratch + BATCH * EMBED)

// ---------------------------------------------------------------------------
// Kernel 1: edge aggregation via cp.async (LDGSTS). Warp owns 32 consecutive
// edges; feature rows are copied gmem->smem with fire-and-forget cp.async
// (no destination registers, no per-load scoreboard): 16 rows in flight per
// warp, 2 batches. Each lane copies/reads ONLY its own 8B slice of each row
// (no cross-lane smem traffic, no syncwarp needed). Register pressure drops
// to ~30 -> 7 blocks/SM (smem-capped) = 56 resident warps.
// Accumulation: register run-compression on sorted seg_ids, atomic flush
// only on segment change (proven R2 design).
// ---------------------------------------------------------------------------
__global__ void __launch_bounds__(256)
agg_kernel(const int*   __restrict__ neigh_ids,
           const int*   __restrict__ seg_ids,
           const float* __restrict__ features) {
    __shared__ float buf[8][16][64];          // 32 KB: 16-row batch per warp

    const int wib  = threadIdx.x >> 5;        // warp in block
    const int lane = threadIdx.x & 31;
    const int warp = blockIdx.x * 8 + wib;
    const int e0   = warp * 32;

    const int my_seg = __ldcs(&seg_ids[e0 + lane]);    // coalesced, streamed
    const int my_nid = __ldcs(&neigh_ids[e0 + lane]);

    // this lane's 8B slice base inside its warp's buffer
    const unsigned dst0 =
        (unsigned)__cvta_generic_to_shared(&buf[wib][0][lane * 2]);

    float2 acc = make_float2(0.0f, 0.0f);
    int cur = __shfl_sync(FULL, my_seg, 0);
    int runlen = 0;

    #pragma unroll
    for (int half = 0; half < 2; ++half) {
        // issue 16 async row copies (each row: 32 lanes x 8B = 256B coalesced)
        #pragma unroll
        for (int u = 0; u < 16; ++u) {
            const int n = __shfl_sync(FULL, my_nid, half * 16 + u);
            const float* src = features + (size_t)n * EMBED + lane * 2;
            asm volatile("cp.async.ca.shared.global [%0], [%1], 8;"
                         :: "r"(dst0 + u * 256), "l"(src));
        }
        asm volatile("cp.async.commit_group;");
        asm volatile("cp.async.wait_group 0;" ::: "memory");

        // consume batch (each lane reads only bytes it copied itself)
        #pragma unroll
        for (int u = 0; u < 16; ++u) {
            const float2 v = *(const float2*)&buf[wib][u][lane * 2];
            const int s = __shfl_sync(FULL, my_seg, half * 16 + u);
            if (s != cur) {               // warp-uniform (s is broadcast)
                atomicAdd(&G_ACC[cur * EMBED + 2 * lane],     acc.x);
                atomicAdd(&G_ACC[cur * EMBED + 2 * lane + 1], acc.y);
                if (lane == 0) atomicAdd(&G_CNT[cur], (float)runlen);
                acc = make_float2(0.0f, 0.0f);
                cur = s;
                runlen = 0;
            }
            acc.x += v.x;
            acc.y += v.y;
            ++runlen;
        }
    }
    atomicAdd(&G_ACC[cur * EMBED + 2 * lane],     acc.x);
    atomicAdd(&G_ACC[cur * EMBED + 2 * lane + 1], acc.y);
    if (lane == 0) atomicAdd(&G_CNT[cur], (float)runlen);
}

// ---------------------------------------------------------------------------
// Kernel 2 (R9 — proven best): self gather + mean + [self|neigh] @ w1^T + b1,
// relu. Register-tiled weights + packed f32x2 FMA; cross-iteration software
// pipeline (ids 2 ahead, rows 1 ahead) into double-buffered comb; w1 staging
// smem union'd with run-phase buffers.
// ---------------------------------------------------------------------------
__global__ void __launch_bounds__(256)
mlp_kernel(const int*   __restrict__ nodes,
           const float* __restrict__ features,
           const float* __restrict__ w1,
           const float* __restrict__ b1,
           float*       __restrict__ out) {
    __shared__ union {
        float w1s[64 * 129];                        // staging (prologue only)
        struct {
            __align__(16) float comb[2][4][128];    // double-buffered concat
            float part[4][64 * 5];                  // stride-5 padded partials
        } run;
    } sm;
    __shared__ float b1s[64];

    const int tid = threadIdx.x;
    const int g = tid >> 6;                         // k-group 0..3
    const int j = tid & 63;                         // output dim
    const int r = g;                                // row for fill/writeback

    for (int idx = tid; idx < 64 * 128; idx += 256) {
        const int jj = idx >> 7;
        const int kk = idx & 127;
        sm.w1s[jj * 129 + kk] = w1[idx];            // w1 row-major (64,128)
    }
    if (tid < 64) b1s[tid] = b1[tid];
    __syncthreads();

    unsigned long long w2[16];
    #pragma unroll
    for (int kk = 0; kk < 16; ++kk) {
        const float lo = sm.w1s[j * 129 + g * 32 + 2 * kk];
        const float hi = sm.w1s[j * 129 + g * 32 + 2 * kk + 1];
        asm("mov.b64 %0, {%1, %2};" : "=l"(w2[kk]) : "f"(lo), "f"(hi));
    }
    __syncthreads();                                // w1s dead; union reused

    const int stride = MLPGRID * 4;
    const int base0  = blockIdx.x * 4;

    int   nodeA = 0;
    float cntA  = 1.0f;

    {
        const int b  = base0 + r;
        const int nd = nodes[b];
        const float c = G_CNT[b];
        sm.run.comb[0][r][j]      = __ldcg(&features[(size_t)nd * EMBED + j]);
        sm.run.comb[0][r][64 + j] = G_ACC[b * EMBED + j] * (1.0f / fmaxf(c, 1.0f));
        const int base1 = base0 + stride;
        if (base1 < BATCH) {
            nodeA = nodes[base1 + r];
            cntA  = G_CNT[base1 + r];
        }
    }
    __syncthreads();

    int cur = 0;
    for (int base = base0; base < BATCH; base += stride) {
        const int base1 = base + stride;
        const int base2 = base + 2 * stride;

        float fN = 0.0f, aN = 0.0f;
        if (base1 < BATCH) {
            fN = __ldcg(&features[(size_t)nodeA * EMBED + j]);
            aN = G_ACC[(base1 + r) * EMBED + j] * (1.0f / fmaxf(cntA, 1.0f));
        }
        int   nodeB = 0;
        float cntB  = 1.0f;
        if (base2 < BATCH) {
            nodeB = nodes[base2 + r];
            cntB  = G_CNT[base2 + r];
        }

        #pragma unroll
        for (int rr = 0; rr < 4; ++rr) {
            const ulonglong2* c2 = (const ulonglong2*)&sm.run.comb[cur][rr][g * 32];
            unsigned long long acc = 0ull;          // packed {0.f, 0.f}
            #pragma unroll
            for (int q = 0; q < 8; ++q) {           // 8 x LDS.128 broadcast
                const ulonglong2 c = c2[q];
                asm("fma.rn.f32x2 %0, %1, %2, %0;"
                    : "+l"(acc) : "l"(c.x), "l"(w2[2 * q]));
                asm("fma.rn.f32x2 %0, %1, %2, %0;"
                    : "+l"(acc) : "l"(c.y), "l"(w2[2 * q + 1]));
            }
            float lo, hi;
            asm("mov.b64 {%0, %1}, %2;" : "=f"(lo), "=f"(hi) : "l"(acc));
            sm.run.part[rr][j * 5 + g] = lo + hi;   // conflict-free (5⊥32)
        }
        __syncthreads();

        {
            const float s = sm.run.part[r][j * 5 + 0] + sm.run.part[r][j * 5 + 1] +
                            sm.run.part[r][j * 5 + 2] + sm.run.part[r][j * 5 + 3] +
                            b1s[j];
            out[(size_t)(base + r) * EMBED + j] = fmaxf(s, 0.0f);
        }
        if (base1 < BATCH) {
            sm.run.comb[cur ^ 1][r][j]      = fN;
            sm.run.comb[cur ^ 1][r][64 + j] = aN;
        }
        nodeA = nodeB;
        cntA  = cntB;
        __syncthreads();
        cur ^= 1;
    }
}

// ---------------------------------------------------------------------------
// Launch — memset node + 2 kernels.
// inputs: nodes(i32,16384) neigh_ids(i32,524288) seg_ids(i32,524288)
//         features(f32,64M) w1(f32,8192) b1(f32,64)   output: f32 (16384,64)
// ---------------------------------------------------------------------------
extern "C" void kernel_launch(void* const* d_in, const int* in_sizes, int n_in,
                              void* d_out, int out_size) {
    const int*   nodes     = (const int*)  d_in[0];
    const int*   neigh_ids = (const int*)  d_in[1];
    const int*   seg_ids   = (const int*)  d_in[2];
    const float* features  = (const float*)d_in[3];
    const float* w1        = (const float*)d_in[4];
    const float* b1        = (const float*)d_in[5];
    float*       out       = (float*)d_out;

    void* scratch_ptr = nullptr;
    cudaGetSymbolAddress(&scratch_ptr, g_scratch);
    cudaMemsetAsync(scratch_ptr, 0,
                    (size_t)(BATCH * EMBED + BATCH) * sizeof(float), 0);

    const int n_warps = N_EDGES / 32;             // 16384 warps, 2048 blocks
    agg_kernel<<<n_warps / 8, 256>>>(neigh_ids, seg_ids, features);

    mlp_kernel<<<MLPGRID, 256>>>(nodes, features, w1, b1, out);
}

// round 13
// speedup vs baseline: 1.1975x; 1.1975x over previous
#include <cuda_runtime.h>
#include <cuda_bf16.h>

#define BATCH   16384
#define EMBED   64
#define N_EDGES 524288
#define FULL    0xffffffffu
#define MLPGRID 592

// Scratch: zero-initialized at module load; the MLP tail re-zeroes exactly
// the rows it consumed, so every launch/replay starts from zeros with NO
// memset node and no cross-block races.
__device__ float g_scratch[BATCH * EMBED + BATCH];
#define G_ACC g_scratch
#define G_CNT (g_scratch + BATCH * EMBED)

// ---------------------------------------------------------------------------
// Kernel 1 (R9 — proven at the DRAM random-gather floor): warp owns 32
// consecutive edges; ids coalesced (.cs) + shfl broadcast; 8 independent
// 256B feature-row loads in flight (.cg); register run-compression on the
// sorted seg_ids, atomic flush only on segment change.
// ---------------------------------------------------------------------------
__global__ void agg_kernel(const int*   __restrict__ neigh_ids,
                           const int*   __restrict__ seg_ids,
                           const float* __restrict__ features) {
    const int warp = (blockIdx.x * blockDim.x + threadIdx.x) >> 5;
    const int lane = threadIdx.x & 31;
    const int e0 = warp * 32;

    const int my_seg = __ldcs(&seg_ids[e0 + lane]);
    const int my_nid = __ldcs(&neigh_ids[e0 + lane]);

    const float2* __restrict__ feats2 = (const float2*)features;

    float2 acc = make_float2(0.0f, 0.0f);
    int cur = __shfl_sync(FULL, my_seg, 0);
    int runlen = 0;

    #pragma unroll
    for (int c = 0; c < 32; c += 8) {
        int    n[8], s[8];
        float2 v[8];
        #pragma unroll
        for (int u = 0; u < 8; ++u) n[u] = __shfl_sync(FULL, my_nid, c + u);
        #pragma unroll
        for (int u = 0; u < 8; ++u)
            v[u] = __ldcg(&feats2[(size_t)n[u] * 32 + lane]);  // L2-only
        #pragma unroll
        for (int u = 0; u < 8; ++u) s[u] = __shfl_sync(FULL, my_seg, c + u);
        #pragma unroll
        for (int u = 0; u < 8; ++u) {
            if (s[u] != cur) {            // warp-uniform (s is broadcast)
                atomicAdd(&G_ACC[cur * EMBED + 2 * lane],     acc.x);
                atomicAdd(&G_ACC[cur * EMBED + 2 * lane + 1], acc.y);
                if (lane == 0) atomicAdd(&G_CNT[cur], (float)runlen);
                acc = make_float2(0.0f, 0.0f);
                cur = s[u];
                runlen = 0;
            }
            acc.x += v[u].x;
            acc.y += v[u].y;
            ++runlen;
        }
    }
    atomicAdd(&G_ACC[cur * EMBED + 2 * lane],     acc.x);
    atomicAdd(&G_ACC[cur * EMBED + 2 * lane + 1], acc.y);
    if (lane == 0) atomicAdd(&G_CNT[cur], (float)runlen);
}

// ---------------------------------------------------------------------------
// Kernel 2: self gather + mean + [self|neigh] @ w1^T + b1, relu.
// DEPTH-2 software pipeline: feature/acc loads for iter i+2 issued at iter i
// (held in regs ~2 iterations), ids for i+3 staged each iter. The mean
// divide is deferred to the partial stage (k-groups 2,3 are exactly the
// neigh half), so the load path ships RAW G_ACC with no cnt dependency.
// Tail: each block zeroes the scratch rows it consumed (replaces memset).
// ---------------------------------------------------------------------------
__global__ void __launch_bounds__(256)
mlp_kernel(const int*   __restrict__ nodes,
           const float* __restrict__ features,
           const float* __restrict__ w1,
           const float* __restrict__ b1,
           float*       __restrict__ out) {
    __shared__ union {
        float w1s[64 * 129];                        // staging (prologue only)
        struct {
            __align__(16) float comb[2][4][128];    // double-buffered concat
            float part[4][64 * 5];                  // stride-5 padded partials
            float invs[2][4];                       // per-row 1/max(cnt,1)
        } run;
    } sm;
    __shared__ float b1s[64];

    const int tid = threadIdx.x;
    const int g = tid >> 6;                         // k-group 0..3 (warp-uni)
    const int j = tid & 63;                         // output dim
    const int r = g;                                // row for fill/writeback

    // ---- prologue: stage w1, fill weight registers, release w1s ----
    for (int idx = tid; idx < 64 * 128; idx += 256) {
        const int jj = idx >> 7;
        const int kk = idx & 127;
        sm.w1s[jj * 129 + kk] = w1[idx];            // w1 row-major (64,128)
    }
    if (tid < 64) b1s[tid] = b1[tid];
    __syncthreads();

    unsigned long long w2[16];
    #pragma unroll
    for (int kk = 0; kk < 16; ++kk) {
        const float lo = sm.w1s[j * 129 + g * 32 + 2 * kk];
        const float hi = sm.w1s[j * 129 + g * 32 + 2 * kk + 1];
        asm("mov.b64 %0, {%1, %2};" : "=l"(w2[kk]) : "f"(lo), "f"(hi));
    }
    __syncthreads();                                // w1s dead; union reused

    const int stride = MLPGRID * 4;
    const int base0  = blockIdx.x * 4;

    // iter 0 filled directly; pipeline regs primed for iters 1 and 2
    {
        const int b = base0 + r;
        const int nd = nodes[b];
        sm.run.comb[0][r][j]      = __ldcg(&features[(size_t)nd * EMBED + j]);
        sm.run.comb[0][r][64 + j] = G_ACC[b * EMBED + j];       // raw sum
        if (j == 0) sm.run.invs[0][r] = 1.0f / fmaxf(G_CNT[b], 1.0f);
    }
    float fA = 0.0f, aA = 0.0f, cntA = 1.0f;        // data for iter 1
    int   nodeB = 0;                                // id   for iter 2
    float cntB = 1.0f;
    {
        const int p1 = base0 + stride, p2 = base0 + 2 * stride;
        if (p1 < BATCH) {
            const int nd1 = nodes[p1 + r];
            cntA = G_CNT[p1 + r];
            fA = __ldcg(&features[(size_t)nd1 * EMBED + j]);
            aA = G_ACC[(p1 + r) * EMBED + j];
        }
        if (p2 < BATCH) { nodeB = nodes[p2 + r]; cntB = G_CNT[p2 + r]; }
    }
    __syncthreads();

    int cur = 0;
    for (int base = base0; base < BATCH; base += stride) {
        const int base1 = base + stride;
        const int base2 = base + 2 * stride;
        const int base3 = base + 3 * stride;

        // issue loads for iter i+2 (arrive ~2 iterations from now)
        float fB = 0.0f, aB = 0.0f;
        if (base2 < BATCH) {
            fB = __ldcg(&features[(size_t)nodeB * EMBED + j]);
            aB = G_ACC[(base2 + r) * EMBED + j];
        }
        // stage ids for iter i+3
        int   nodeC = 0;
        float cntC = 1.0f;
        if (base3 < BATCH) { nodeC = nodes[base3 + r]; cntC = G_CNT[base3 + r]; }

        // partials from comb[cur]; neigh k-groups (g>=2) scaled by inv
        #pragma unroll
        for (int rr = 0; rr < 4; ++rr) {
            const ulonglong2* c2 = (const ulonglong2*)&sm.run.comb[cur][rr][g * 32];
            unsigned long long acc = 0ull;          // packed {0.f, 0.f}
            #pragma unroll
            for (int q = 0; q < 8; ++q) {           // 8 x LDS.128 broadcast
                const ulonglong2 c = c2[q];
                asm("fma.rn.f32x2 %0, %1, %2, %0;"
                    : "+l"(acc) : "l"(c.x), "l"(w2[2 * q]));
                asm("fma.rn.f32x2 %0, %1, %2, %0;"
                    : "+l"(acc) : "l"(c.y), "l"(w2[2 * q + 1]));
            }
            float lo, hi;
            asm("mov.b64 {%0, %1}, %2;" : "=f"(lo), "=f"(hi) : "l"(acc));
            const float m = (g >= 2) ? sm.run.invs[cur][rr] : 1.0f;
            sm.run.part[rr][j * 5 + g] = (lo + hi) * m;   // conflict-free
        }
        __syncthreads();

        // reduce + bias + relu + store
        {
            const float s = sm.run.part[r][j * 5 + 0] + sm.run.part[r][j * 5 + 1] +
                            sm.run.part[r][j * 5 + 2] + sm.run.part[r][j * 5 + 3] +
                            b1s[j];
            out[(size_t)(base + r) * EMBED + j] = fmaxf(s, 0.0f);
        }
        // store arrived data for iter i+1 into the other buffer
        if (base1 < BATCH) {
            sm.run.comb[cur ^ 1][r][j]      = fA;
            sm.run.comb[cur ^ 1][r][64 + j] = aA;
            if (j == 0) sm.run.invs[cur ^ 1][r] = 1.0f / fmaxf(cntA, 1.0f);
        }
        // shift pipeline registers
        fA = fB;  aA = aB;  cntA = cntB;  cntB = cntC;  nodeB = nodeC;
        __syncthreads();
        cur ^= 1;
    }

    // ---- tail: zero exactly the scratch rows this block consumed ----
    for (int base = base0; base < BATCH; base += stride) {
        G_ACC[(base + r) * EMBED + j] = 0.0f;       // coalesced, own rows only
        if (j == 0) G_CNT[base + r] = 0.0f;
    }
}

// ---------------------------------------------------------------------------
// Launch — two kernels, no memset node.
// inputs: nodes(i32,16384) neigh_ids(i32,524288) seg_ids(i32,524288)
//         features(f32,64M) w1(f32,8192) b1(f32,64)   output: f32 (16384,64)
// ---------------------------------------------------------------------------
extern "C" void kernel_launch(void* const* d_in, const int* in_sizes, int n_in,
                              void* d_out, int out_size) {
    const int*   nodes     = (const int*)  d_in[0];
    const int*   neigh_ids = (const int*)  d_in[1];
    const int*   seg_ids   = (const int*)  d_in[2];
    const float* features  = (const float*)d_in[3];
    const float* w1        = (const float*)d_in[4];
    const float* b1        = (const float*)d_in[5];
    float*       out       = (float*)d_out;

    const int n_warps = N_EDGES / 32;             // 16384 warps, 2048 blocks
    agg_kernel<<<n_warps / 8, 256>>>(neigh_ids, seg_ids, features);

    mlp_kernel<<<MLPGRID, 256>>>(nodes, features, w1, b1, out);
}